// round 1
// baseline (speedup 1.0000x reference)
#include <cuda_runtime.h>
#include <cuda_bf16.h>

#define NB    2048          // batch per view
#define N2    4096          // 2B rows
#define DDIM  1024          // feature dim
#define INV_T 14.2857142857142857f   // 1/0.07

// Scratch (device globals: no allocation allowed in kernel_launch)
__device__ __align__(256) float g_zn[N2 * DDIM];   // normalized rows, fp32
__device__ float g_denom[N2];
__device__ float g_pos[N2];

// ---------------------------------------------------------------------------
// Kernel 1: L2-normalize. One block per output row r.
//   r < 2048  -> features[r, 0, :]
//   r >= 2048 -> features[r-2048, 1, :]
// Also zeroes g_denom / g_pos so every graph replay is deterministic.
// ---------------------------------------------------------------------------
__global__ void __launch_bounds__(256) norm_kernel(const float* __restrict__ feat)
{
    const int r = blockIdx.x;
    const int b = r & (NB - 1);
    const int v = r >> 11;
    const float* __restrict__ src = feat + ((size_t)b * 2 + v) * DDIM;

    const int t = threadIdx.x;            // 256 threads, 4 contiguous floats each
    float4 x = reinterpret_cast<const float4*>(src)[t];
    float ss = x.x * x.x + x.y * x.y + x.z * x.z + x.w * x.w;

    // warp reduce
    #pragma unroll
    for (int o = 16; o; o >>= 1) ss += __shfl_xor_sync(0xffffffffu, ss, o);

    __shared__ float ws[8];
    if ((t & 31) == 0) ws[t >> 5] = ss;
    __syncthreads();
    float tot = 0.f;
    #pragma unroll
    for (int i = 0; i < 8; ++i) tot += ws[i];

    const float nrm = sqrtf(tot);
    const float inv = 1.0f / fmaxf(nrm, 1e-12f);

    float4 y = make_float4(x.x * inv, x.y * inv, x.z * inv, x.w * inv);
    reinterpret_cast<float4*>(g_zn + (size_t)r * DDIM)[t] = y;

    if (t == 0) { g_denom[r] = 0.0f; g_pos[r] = 0.0f; }
}

// ---------------------------------------------------------------------------
// Kernel 2: fused sim-tile GEMM + exp epilogue.
// Grid: (64 row-blocks of 64 rows) x (4 column splits of 1024 cols).
// Block: 256 threads = 16x16; each thread owns a 4x4 microtile with
// rows m = ty + 16*i, cols n = tx + 16*j (conflict-free smem reads).
// ---------------------------------------------------------------------------
#define TM 64
#define TN 64
#define BK 32

__global__ void __launch_bounds__(256) loss_tiles_kernel()
{
    __shared__ float As[TM][BK + 1];   // [64][33] padded
    __shared__ float Bs[TN][BK + 1];

    const int t  = threadIdx.x;
    const int tx = t & 15;
    const int ty = t >> 4;
    const int row0      = blockIdx.x * TM;
    const int col_base  = blockIdx.y * 1024;

    float denom[4] = {0.f, 0.f, 0.f, 0.f};

    for (int ct = 0; ct < 16; ++ct) {
        const int col0 = col_base + ct * TN;

        float acc[4][4];
        #pragma unroll
        for (int i = 0; i < 4; ++i)
            #pragma unroll
            for (int j = 0; j < 4; ++j) acc[i][j] = 0.f;

        for (int kt = 0; kt < DDIM / BK; ++kt) {
            const int k0 = kt * BK;
            __syncthreads();
            // Load A (64x32) and B (64x32) tiles: 512 float4 each, 2/thread.
            #pragma unroll
            for (int s = 0; s < 2; ++s) {
                const int idx = t + 256 * s;     // 0..511
                const int m   = idx >> 3;        // row within tile
                const int kq  = idx & 7;         // float4 index within 32-k chunk
                float4 a = *reinterpret_cast<const float4*>(
                    g_zn + (size_t)(row0 + m) * DDIM + k0 + kq * 4);
                As[m][kq * 4 + 0] = a.x; As[m][kq * 4 + 1] = a.y;
                As[m][kq * 4 + 2] = a.z; As[m][kq * 4 + 3] = a.w;
                float4 bv = *reinterpret_cast<const float4*>(
                    g_zn + (size_t)(col0 + m) * DDIM + k0 + kq * 4);
                Bs[m][kq * 4 + 0] = bv.x; Bs[m][kq * 4 + 1] = bv.y;
                Bs[m][kq * 4 + 2] = bv.z; Bs[m][kq * 4 + 3] = bv.w;
            }
            __syncthreads();

            #pragma unroll
            for (int k = 0; k < BK; ++k) {
                const float a0 = As[ty     ][k];
                const float a1 = As[ty + 16][k];
                const float a2 = As[ty + 32][k];
                const float a3 = As[ty + 48][k];
                const float b0 = Bs[tx     ][k];
                const float b1 = Bs[tx + 16][k];
                const float b2 = Bs[tx + 32][k];
                const float b3 = Bs[tx + 48][k];
                acc[0][0] += a0 * b0; acc[0][1] += a0 * b1; acc[0][2] += a0 * b2; acc[0][3] += a0 * b3;
                acc[1][0] += a1 * b0; acc[1][1] += a1 * b1; acc[1][2] += a1 * b2; acc[1][3] += a1 * b3;
                acc[2][0] += a2 * b0; acc[2][1] += a2 * b1; acc[2][2] += a2 * b2; acc[2][3] += a2 * b3;
                acc[3][0] += a3 * b0; acc[3][1] += a3 * b1; acc[3][2] += a3 * b2; acc[3][3] += a3 * b3;
            }
        }

        // Fused epilogue on this 64x64 tile
        #pragma unroll
        for (int i = 0; i < 4; ++i) {
            const int r    = row0 + ty + 16 * i;
            const int pcol = (r < NB) ? (r + NB) : (r - NB);
            #pragma unroll
            for (int j = 0; j < 4; ++j) {
                const int c = col0 + tx + 16 * j;
                const float s = acc[i][j];
                if (c != r) denom[i] += __expf(s * INV_T);
                if (c == pcol) g_pos[r] = s;   // exactly one writer chip-wide
            }
        }
    }

    // Reduce denom[i] across the 16 tx lanes (half-warp) and accumulate.
    #pragma unroll
    for (int i = 0; i < 4; ++i) {
        float v = denom[i];
        #pragma unroll
        for (int o = 8; o; o >>= 1) v += __shfl_down_sync(0xffffffffu, v, o);
        if (tx == 0) atomicAdd(&g_denom[row0 + ty + 16 * i], v);
    }
}

// ---------------------------------------------------------------------------
// Kernel 3: finalize — per-row loss, mean over 4096 rows.
// ---------------------------------------------------------------------------
__global__ void __launch_bounds__(512) finalize_kernel(float* __restrict__ out)
{
    const int t = threadIdx.x;
    float acc = 0.f;
    for (int r = t; r < N2; r += 512)
        acc += -(g_pos[r] * INV_T - logf(g_denom[r]));

    #pragma unroll
    for (int o = 16; o; o >>= 1) acc += __shfl_xor_sync(0xffffffffu, acc, o);
    __shared__ float ws[16];
    if ((t & 31) == 0) ws[t >> 5] = acc;
    __syncthreads();
    if (t == 0) {
        float tot = 0.f;
        #pragma unroll
        for (int i = 0; i < 16; ++i) tot += ws[i];
        out[0] = tot / (float)N2;
    }
}

// ---------------------------------------------------------------------------
extern "C" void kernel_launch(void* const* d_in, const int* in_sizes, int n_in,
                              void* d_out, int out_size)
{
    const float* feat = (const float*)d_in[0];
    float* out = (float*)d_out;

    norm_kernel<<<N2, 256>>>(feat);
    loss_tiles_kernel<<<dim3(N2 / TM, 4), 256>>>();
    finalize_kernel<<<1, 512>>>(out);
}

// round 3
// speedup vs baseline: 11.9918x; 11.9918x over previous
#include <cuda_runtime.h>
#include <cuda_bf16.h>
#include <cstdint>

#define NB    2048
#define N2    4096
#define DDIM  1024
#define INV_T 14.285714285714286f

#define BM 128
#define BN 128
#define BK 64                 // bf16 k-chunk: 128 bytes/row
#define NSTAGE 3
#define STAGE_BYTES (2 * BM * 128)          // A tile + B tile = 32KB
#define DYN_SMEM (NSTAGE * STAGE_BYTES)     // 96KB

// ---------------- device globals -------------------------------------------
__device__ __align__(256) __nv_bfloat16 g_zn[N2 * DDIM];   // normalized, bf16
__device__ float g_denom[N2];
__device__ float g_pos[N2];

// ---------------- asm helpers ----------------------------------------------
__device__ __forceinline__ uint32_t smem_u32(const void* p) {
    uint32_t a;
    asm("{ .reg .u64 t; cvta.to.shared.u64 t, %1; cvt.u32.u64 %0, t; }"
        : "=r"(a) : "l"(p));
    return a;
}

#define CP_ASYNC16(dst, src) \
    asm volatile("cp.async.cg.shared.global [%0], [%1], 16;" :: "r"(dst), "l"(src))
#define CP_COMMIT() asm volatile("cp.async.commit_group;" ::: "memory")
#define CP_WAIT1()  asm volatile("cp.async.wait_group 1;" ::: "memory")

#define LDSM_X4(r, addr)                                                      \
    asm volatile("ldmatrix.sync.aligned.m8n8.x4.shared.b16 {%0,%1,%2,%3}, [%4];" \
        : "=r"((r)[0]), "=r"((r)[1]), "=r"((r)[2]), "=r"((r)[3]) : "r"(addr))

#define MMA16816(d, a, b0, b1)                                                \
    asm volatile("mma.sync.aligned.m16n8k16.row.col.f32.bf16.bf16.f32 "       \
        "{%0,%1,%2,%3}, {%4,%5,%6,%7}, {%8,%9}, {%0,%1,%2,%3};"               \
        : "+f"((d)[0]), "+f"((d)[1]), "+f"((d)[2]), "+f"((d)[3])              \
        : "r"((a)[0]), "r"((a)[1]), "r"((a)[2]), "r"((a)[3]),                 \
          "r"(b0), "r"(b1))

// ---------------------------------------------------------------------------
// Kernel 1: L2-normalize + bf16 quantize, row-major output. Zeroes accums.
// ---------------------------------------------------------------------------
__global__ void __launch_bounds__(256) norm_kernel(const float* __restrict__ feat)
{
    const int r = blockIdx.x;
    const int b = r & (NB - 1);
    const int v = r >> 11;
    const float* __restrict__ src = feat + ((size_t)b * 2 + v) * DDIM;

    const int t = threadIdx.x;
    float4 x = reinterpret_cast<const float4*>(src)[t];
    float ss = x.x * x.x + x.y * x.y + x.z * x.z + x.w * x.w;
    #pragma unroll
    for (int o = 16; o; o >>= 1) ss += __shfl_xor_sync(0xffffffffu, ss, o);
    __shared__ float ws[8];
    if ((t & 31) == 0) ws[t >> 5] = ss;
    __syncthreads();
    float tot = 0.f;
    #pragma unroll
    for (int i = 0; i < 8; ++i) tot += ws[i];
    const float inv = 1.0f / fmaxf(sqrtf(tot), 1e-12f);

    __nv_bfloat162 p01 = __floats2bfloat162_rn(x.x * inv, x.y * inv);
    __nv_bfloat162 p23 = __floats2bfloat162_rn(x.z * inv, x.w * inv);
    uint2 val;
    val.x = *reinterpret_cast<uint32_t*>(&p01);
    val.y = *reinterpret_cast<uint32_t*>(&p23);
    reinterpret_cast<uint2*>(g_zn + (size_t)r * DDIM)[t] = val;

    if (t == 0) { g_denom[r] = 0.0f; g_pos[r] = 0.0f; }
}

// ---------------------------------------------------------------------------
// Kernel 2: bf16 mma.sync GEMM tile (128x128) + fused exp epilogue.
// 256 threads = 8 warps (4 along M x 2 along N); warp tile 32x64.
// ---------------------------------------------------------------------------
__global__ void __launch_bounds__(256, 2) simloss_kernel()
{
    extern __shared__ __align__(128) unsigned char dynsmem[];
    const uint32_t smem_base = smem_u32(dynsmem);

    const int tid    = threadIdx.x;
    const int lane   = tid & 31;
    const int warp   = tid >> 5;
    const int warp_m = warp & 3;
    const int warp_n = warp >> 2;
    const int row0   = blockIdx.y * BM;
    const int col0   = blockIdx.x * BN;

    // ---- cp.async stage loader (A tile rows=row0.., B tile rows=col0..) ----
    auto load_stage = [&](int stage, int kc) {
        const uint32_t sA = smem_base + stage * STAGE_BYTES;
        const uint32_t sB = sA + BM * 128;
        #pragma unroll
        for (int i = 0; i < 4; ++i) {
            const int idx  = tid + i * 256;       // 0..1023
            const int rr   = idx >> 3;            // row in tile 0..127
            const int c16  = idx & 7;             // 16B chunk 0..7
            const uint32_t sw = (uint32_t)((c16 * 16) ^ ((rr & 7) << 4));
            const char* gA = (const char*)g_zn +
                (((size_t)(row0 + rr) * DDIM + kc * BK) * 2 + c16 * 16);
            const char* gB = (const char*)g_zn +
                (((size_t)(col0 + rr) * DDIM + kc * BK) * 2 + c16 * 16);
            CP_ASYNC16(sA + rr * 128 + sw, gA);
            CP_ASYNC16(sB + rr * 128 + sw, gB);
        }
        CP_COMMIT();
    };

    float acc[2][4][2][4];
    #pragma unroll
    for (int mi = 0; mi < 2; ++mi)
        #pragma unroll
        for (int ni = 0; ni < 4; ++ni)
            #pragma unroll
            for (int h = 0; h < 2; ++h)
                #pragma unroll
                for (int e = 0; e < 4; ++e) acc[mi][ni][h][e] = 0.f;

    load_stage(0, 0);
    load_stage(1, 1);

    // ldmatrix lane addressing (constant parts)
    const uint32_t lrow = (uint32_t)(lane & 15);
    const uint32_t hi16 = (uint32_t)((lane >> 4) * 16);
    const uint32_t swz  = (lrow & 7) << 4;
    const uint32_t aRowOff = (uint32_t)((warp_m * 32 + lrow) * 128);
    const uint32_t bRowOff = (uint32_t)(BM * 128 + (warp_n * 64 + lrow) * 128);

    const int NCHUNK = DDIM / BK;   // 16
    for (int kc = 0; kc < NCHUNK; ++kc) {
        CP_WAIT1();
        __syncthreads();
        if (kc + 2 < NCHUNK) load_stage((kc + 2) % NSTAGE, kc + 2);

        const uint32_t sBase = smem_base + (kc % NSTAGE) * STAGE_BYTES;
        const uint32_t aBase = sBase + aRowOff;
        const uint32_t bBase = sBase + bRowOff;

        #pragma unroll
        for (int ks = 0; ks < 4; ++ks) {
            const uint32_t off = (uint32_t)((ks * 32 + hi16)) ^ swz;
            uint32_t a[2][4], b[4][4];
            LDSM_X4(a[0], aBase + off);
            LDSM_X4(a[1], aBase + 16 * 128 + off);
            #pragma unroll
            for (int ni = 0; ni < 4; ++ni)
                LDSM_X4(b[ni], bBase + ni * 16 * 128 + off);

            #pragma unroll
            for (int mi = 0; mi < 2; ++mi)
                #pragma unroll
                for (int ni = 0; ni < 4; ++ni) {
                    MMA16816(acc[mi][ni][0], a[mi], b[ni][0], b[ni][2]);
                    MMA16816(acc[mi][ni][1], a[mi], b[ni][1], b[ni][3]);
                }
        }
        __syncthreads();
    }

    // ---- fused epilogue: exp, diagonal mask, positives, row-denominators ---
    #pragma unroll
    for (int mi = 0; mi < 2; ++mi) {
        float rsum0 = 0.f, rsum1 = 0.f;   // row t/4 and row t/4+8
        const int mbase = row0 + warp_m * 32 + mi * 16 + (lane >> 2);
        #pragma unroll
        for (int ni = 0; ni < 4; ++ni)
            #pragma unroll
            for (int h = 0; h < 2; ++h) {
                const int nbase = col0 + warp_n * 64 + ni * 16 + h * 8 + (lane & 3) * 2;
                #pragma unroll
                for (int e = 0; e < 4; ++e) {
                    const int m = mbase + (e >> 1) * 8;
                    const int n = nbase + (e & 1);
                    const float v = acc[mi][ni][h][e];
                    if (n == (m ^ 2048)) g_pos[m] = v;
                    const float ev = (n != m) ? __expf(v * INV_T) : 0.f;
                    if (e >> 1) rsum1 += ev; else rsum0 += ev;
                }
            }
        rsum0 += __shfl_down_sync(0xffffffffu, rsum0, 2);
        rsum0 += __shfl_down_sync(0xffffffffu, rsum0, 1);
        rsum1 += __shfl_down_sync(0xffffffffu, rsum1, 2);
        rsum1 += __shfl_down_sync(0xffffffffu, rsum1, 1);
        if ((lane & 3) == 0) {
            atomicAdd(&g_denom[mbase], rsum0);
            atomicAdd(&g_denom[mbase + 8], rsum1);
        }
    }
}

// ---------------------------------------------------------------------------
// Kernel 3: finalize — per-row loss, mean over 4096 rows.
// ---------------------------------------------------------------------------
__global__ void __launch_bounds__(512) finalize_kernel(float* __restrict__ out)
{
    const int t = threadIdx.x;
    float acc = 0.f;
    for (int r = t; r < N2; r += 512)
        acc += -(g_pos[r] * INV_T - logf(g_denom[r]));
    #pragma unroll
    for (int o = 16; o; o >>= 1) acc += __shfl_xor_sync(0xffffffffu, acc, o);
    __shared__ float ws[16];
    if ((t & 31) == 0) ws[t >> 5] = acc;
    __syncthreads();
    if (t == 0) {
        float tot = 0.f;
        #pragma unroll
        for (int i = 0; i < 16; ++i) tot += ws[i];
        out[0] = tot / (float)N2;
    }
}

// ---------------------------------------------------------------------------
extern "C" void kernel_launch(void* const* d_in, const int* in_sizes, int n_in,
                              void* d_out, int out_size)
{
    const float* feat = (const float*)d_in[0];
    float* out = (float*)d_out;

    cudaFuncSetAttribute(simloss_kernel,
                         cudaFuncAttributeMaxDynamicSharedMemorySize, DYN_SMEM);

    norm_kernel<<<N2, 256>>>(feat);
    simloss_kernel<<<dim3(BN == 128 ? N2 / BN : 0 ? 0 : N2 / BN, N2 / BM), 256, DYN_SMEM>>>();
    finalize_kernel<<<1, 512>>>(out);
}

// round 4
// speedup vs baseline: 17.9904x; 1.5002x over previous
#include <cuda_runtime.h>
#include <cuda_bf16.h>
#include <cstdint>

#define NB    2048
#define N2    4096
#define DDIM  1024
#define INV_T 14.285714285714286f

#define BM 128
#define BN 128
#define BK 64                 // bf16 k-chunk: 128 bytes/row
#define NSTAGE 3
#define STAGE_BYTES (2 * BM * 128)          // A tile + B tile = 32KB
#define DYN_SMEM (NSTAGE * STAGE_BYTES)     // 96KB
#define NTILES_UT 528                        // 32*33/2 upper-tri 128x128 tiles

// ---------------- device globals -------------------------------------------
__device__ __align__(256) __nv_bfloat16 g_zn[N2 * DDIM];   // normalized, bf16
__device__ float g_denom[N2];
__device__ float g_pos[N2];

// ---------------- asm helpers ----------------------------------------------
__device__ __forceinline__ uint32_t smem_u32(const void* p) {
    uint32_t a;
    asm("{ .reg .u64 t; cvta.to.shared.u64 t, %1; cvt.u32.u64 %0, t; }"
        : "=r"(a) : "l"(p));
    return a;
}

#define CP_ASYNC16(dst, src) \
    asm volatile("cp.async.cg.shared.global [%0], [%1], 16;" :: "r"(dst), "l"(src))
#define CP_COMMIT() asm volatile("cp.async.commit_group;" ::: "memory")
#define CP_WAIT1()  asm volatile("cp.async.wait_group 1;" ::: "memory")

#define LDSM_X4(r, addr)                                                      \
    asm volatile("ldmatrix.sync.aligned.m8n8.x4.shared.b16 {%0,%1,%2,%3}, [%4];" \
        : "=r"((r)[0]), "=r"((r)[1]), "=r"((r)[2]), "=r"((r)[3]) : "r"(addr))

#define MMA16816(d, a, b0, b1)                                                \
    asm volatile("mma.sync.aligned.m16n8k16.row.col.f32.bf16.bf16.f32 "       \
        "{%0,%1,%2,%3}, {%4,%5,%6,%7}, {%8,%9}, {%0,%1,%2,%3};"               \
        : "+f"((d)[0]), "+f"((d)[1]), "+f"((d)[2]), "+f"((d)[3])              \
        : "r"((a)[0]), "r"((a)[1]), "r"((a)[2]), "r"((a)[3]),                 \
          "r"(b0), "r"(b1))

// ---------------------------------------------------------------------------
// Kernel 1: L2-normalize + bf16 quantize, row-major output. Zeroes accums.
// ---------------------------------------------------------------------------
__global__ void __launch_bounds__(256) norm_kernel(const float* __restrict__ feat)
{
    const int r = blockIdx.x;
    const int b = r & (NB - 1);
    const int v = r >> 11;
    const float* __restrict__ src = feat + ((size_t)b * 2 + v) * DDIM;

    const int t = threadIdx.x;
    float4 x = reinterpret_cast<const float4*>(src)[t];
    float ss = x.x * x.x + x.y * x.y + x.z * x.z + x.w * x.w;
    #pragma unroll
    for (int o = 16; o; o >>= 1) ss += __shfl_xor_sync(0xffffffffu, ss, o);
    __shared__ float ws[8];
    if ((t & 31) == 0) ws[t >> 5] = ss;
    __syncthreads();
    float tot = 0.f;
    #pragma unroll
    for (int i = 0; i < 8; ++i) tot += ws[i];
    const float inv = 1.0f / fmaxf(sqrtf(tot), 1e-12f);

    __nv_bfloat162 p01 = __floats2bfloat162_rn(x.x * inv, x.y * inv);
    __nv_bfloat162 p23 = __floats2bfloat162_rn(x.z * inv, x.w * inv);
    uint2 val;
    val.x = *reinterpret_cast<uint32_t*>(&p01);
    val.y = *reinterpret_cast<uint32_t*>(&p23);
    reinterpret_cast<uint2*>(g_zn + (size_t)r * DDIM)[t] = val;

    if (t == 0) { g_denom[r] = 0.0f; g_pos[r] = 0.0f; }
}

// ---------------------------------------------------------------------------
// Kernel 2: upper-triangular bf16 GEMM tiles + symmetric exp epilogue.
// 256 threads = 8 warps (4 along M x 2 along N); warp tile 32x64.
// Off-diagonal tile (bi<bj): exp values feed row sums AND column sums.
// Diagonal tile (bi==bj): row sums only; B tile aliases A tile (half traffic).
// ---------------------------------------------------------------------------
__global__ void __launch_bounds__(256, 2) simloss_kernel()
{
    extern __shared__ __align__(128) unsigned char dynsmem[];
    const uint32_t smem_base = smem_u32(dynsmem);

    // Map linear tile id -> (bi, bj) in upper triangle (row-major by bi).
    int rem = blockIdx.x, bi = 0;
    while (rem >= 32 - bi) { rem -= 32 - bi; ++bi; }
    const int bj = bi + rem;
    const bool diag = (bi == bj);

    const int tid    = threadIdx.x;
    const int lane   = tid & 31;
    const int warp   = tid >> 5;
    const int warp_m = warp & 3;
    const int warp_n = warp >> 2;
    const int row0   = bi * BM;
    const int col0   = bj * BN;

    // ---- cp.async stage loader ----
    auto load_stage = [&](int stage, int kc) {
        const uint32_t sA = smem_base + stage * STAGE_BYTES;
        const uint32_t sB = sA + BM * 128;
        #pragma unroll
        for (int i = 0; i < 4; ++i) {
            const int idx  = tid + i * 256;       // 0..1023
            const int rr   = idx >> 3;            // row in tile 0..127
            const int c16  = idx & 7;             // 16B chunk 0..7
            const uint32_t sw = (uint32_t)((c16 * 16) ^ ((rr & 7) << 4));
            const char* gA = (const char*)g_zn +
                (((size_t)(row0 + rr) * DDIM + kc * BK) * 2 + c16 * 16);
            CP_ASYNC16(sA + rr * 128 + sw, gA);
            if (!diag) {
                const char* gB = (const char*)g_zn +
                    (((size_t)(col0 + rr) * DDIM + kc * BK) * 2 + c16 * 16);
                CP_ASYNC16(sB + rr * 128 + sw, gB);
            }
        }
        CP_COMMIT();
    };

    float acc[2][4][2][4];
    #pragma unroll
    for (int mi = 0; mi < 2; ++mi)
        #pragma unroll
        for (int ni = 0; ni < 4; ++ni)
            #pragma unroll
            for (int h = 0; h < 2; ++h)
                #pragma unroll
                for (int e = 0; e < 4; ++e) acc[mi][ni][h][e] = 0.f;

    load_stage(0, 0);
    load_stage(1, 1);

    const uint32_t lrow = (uint32_t)(lane & 15);
    const uint32_t hi16 = (uint32_t)((lane >> 4) * 16);
    const uint32_t swz  = (lrow & 7) << 4;
    const uint32_t aRowOff = (uint32_t)((warp_m * 32 + lrow) * 128);
    const uint32_t bRowOff = (uint32_t)((diag ? 0 : BM * 128) +
                                        (warp_n * 64 + lrow) * 128);

    const int NCHUNK = DDIM / BK;   // 16
    for (int kc = 0; kc < NCHUNK; ++kc) {
        CP_WAIT1();
        __syncthreads();
        if (kc + 2 < NCHUNK) load_stage((kc + 2) % NSTAGE, kc + 2);

        const uint32_t sBase = smem_base + (kc % NSTAGE) * STAGE_BYTES;
        const uint32_t aBase = sBase + aRowOff;
        const uint32_t bBase = sBase + bRowOff;

        #pragma unroll
        for (int ks = 0; ks < 4; ++ks) {
            const uint32_t off = (uint32_t)((ks * 32 + hi16)) ^ swz;
            uint32_t a[2][4], b[4][4];
            LDSM_X4(a[0], aBase + off);
            LDSM_X4(a[1], aBase + 16 * 128 + off);
            #pragma unroll
            for (int ni = 0; ni < 4; ++ni)
                LDSM_X4(b[ni], bBase + ni * 16 * 128 + off);

            #pragma unroll
            for (int mi = 0; mi < 2; ++mi)
                #pragma unroll
                for (int ni = 0; ni < 4; ++ni) {
                    MMA16816(acc[mi][ni][0], a[mi], b[ni][0], b[ni][2]);
                    MMA16816(acc[mi][ni][1], a[mi], b[ni][1], b[ni][3]);
                }
        }
        __syncthreads();
    }

    // ---- fused symmetric epilogue ------------------------------------------
    float csum[4][2][2];
    #pragma unroll
    for (int ni = 0; ni < 4; ++ni)
        #pragma unroll
        for (int h = 0; h < 2; ++h) { csum[ni][h][0] = 0.f; csum[ni][h][1] = 0.f; }

    #pragma unroll
    for (int mi = 0; mi < 2; ++mi) {
        float rsum0 = 0.f, rsum1 = 0.f;
        const int mbase = row0 + warp_m * 32 + mi * 16 + (lane >> 2);
        #pragma unroll
        for (int ni = 0; ni < 4; ++ni)
            #pragma unroll
            for (int h = 0; h < 2; ++h) {
                const int nbase = col0 + warp_n * 64 + ni * 16 + h * 8 + (lane & 3) * 2;
                #pragma unroll
                for (int e = 0; e < 4; ++e) {
                    const int m = mbase + (e >> 1) * 8;
                    const int n = nbase + (e & 1);
                    const float v = acc[mi][ni][h][e];
                    if (!diag && n == (m ^ 2048)) { g_pos[m] = v; g_pos[n] = v; }
                    const float ev = (diag && n == m) ? 0.f : __expf(v * INV_T);
                    if (e >> 1) rsum1 += ev; else rsum0 += ev;
                    if (!diag) csum[ni][h][e & 1] += ev;
                }
            }
        rsum0 += __shfl_down_sync(0xffffffffu, rsum0, 2);
        rsum0 += __shfl_down_sync(0xffffffffu, rsum0, 1);
        rsum1 += __shfl_down_sync(0xffffffffu, rsum1, 2);
        rsum1 += __shfl_down_sync(0xffffffffu, rsum1, 1);
        if ((lane & 3) == 0) {
            atomicAdd(&g_denom[mbase], rsum0);
            atomicAdd(&g_denom[mbase + 8], rsum1);
        }
    }

    if (!diag) {
        // Column sums: reduce across the 8 row-lanes (bits 2..4 of lane).
        #pragma unroll
        for (int ni = 0; ni < 4; ++ni)
            #pragma unroll
            for (int h = 0; h < 2; ++h)
                #pragma unroll
                for (int p = 0; p < 2; ++p) {
                    float c = csum[ni][h][p];
                    c += __shfl_xor_sync(0xffffffffu, c, 4);
                    c += __shfl_xor_sync(0xffffffffu, c, 8);
                    c += __shfl_xor_sync(0xffffffffu, c, 16);
                    if (lane < 4)
                        atomicAdd(&g_denom[col0 + warp_n * 64 + ni * 16 + h * 8 +
                                           lane * 2 + p], c);
                }
    }
}

// ---------------------------------------------------------------------------
// Kernel 3: finalize — per-row loss, mean over 4096 rows.
// ---------------------------------------------------------------------------
__global__ void __launch_bounds__(512) finalize_kernel(float* __restrict__ out)
{
    const int t = threadIdx.x;
    float acc = 0.f;
    for (int r = t; r < N2; r += 512)
        acc += -(g_pos[r] * INV_T - logf(g_denom[r]));
    #pragma unroll
    for (int o = 16; o; o >>= 1) acc += __shfl_xor_sync(0xffffffffu, acc, o);
    __shared__ float ws[16];
    if ((t & 31) == 0) ws[t >> 5] = acc;
    __syncthreads();
    if (t == 0) {
        float tot = 0.f;
        #pragma unroll
        for (int i = 0; i < 16; ++i) tot += ws[i];
        out[0] = tot / (float)N2;
    }
}

// ---------------------------------------------------------------------------
extern "C" void kernel_launch(void* const* d_in, const int* in_sizes, int n_in,
                              void* d_out, int out_size)
{
    const float* feat = (const float*)d_in[0];
    float* out = (float*)d_out;

    cudaFuncSetAttribute(simloss_kernel,
                         cudaFuncAttributeMaxDynamicSharedMemorySize, DYN_SMEM);

    norm_kernel<<<N2, 256>>>(feat);
    simloss_kernel<<<NTILES_UT, 256, DYN_SMEM>>>();
    finalize_kernel<<<1, 512>>>(out);
}

// round 5
// speedup vs baseline: 19.7184x; 1.0960x over previous
#include <cuda_runtime.h>
#include <cuda_bf16.h>
#include <cstdint>

#define NB    2048
#define N2    4096
#define DDIM  1024
#define INV_T 14.285714285714286f

#define BM 128
#define BN 128
#define BK 64                 // bf16 k-chunk: 128 bytes/row
#define NSTAGE 3
#define BLK_BYTES 16384                     // one 128x64 bf16 swizzled block
#define STAGE_BYTES (2 * BLK_BYTES)         // A + B = 32KB
#define DYN_SMEM (NSTAGE * STAGE_BYTES)     // 96KB
#define ROW_TILES 32
#define NCHUNK 16
#define NTILES_UT 528                        // 32*33/2 upper-tri tiles

// ---------------- device globals -------------------------------------------
// Z bf16, pre-swizzled 16KB blocks: g_zb[(kc*ROW_TILES + rowtile)*16384]
__device__ __align__(1024) unsigned char g_zb[NCHUNK * ROW_TILES * BLK_BYTES];
__device__ float g_denom[N2];
__device__ float g_pos[N2];

// ---------------- asm helpers ----------------------------------------------
__device__ __forceinline__ uint32_t smem_u32(const void* p) {
    uint32_t a;
    asm("{ .reg .u64 t; cvta.to.shared.u64 t, %1; cvt.u32.u64 %0, t; }"
        : "=r"(a) : "l"(p));
    return a;
}

#define MBAR_INIT(addr, cnt) \
    asm volatile("mbarrier.init.shared.b64 [%0], %1;" :: "r"(addr), "r"(cnt) : "memory")
#define MBAR_EXPECT_TX(addr, bytes) \
    asm volatile("mbarrier.arrive.expect_tx.shared.b64 _, [%0], %1;" :: "r"(addr), "r"(bytes) : "memory")

#define MBAR_WAIT(addr, parity) do {                                          \
    uint32_t _m = (addr), _p = (uint32_t)(parity), _d;                        \
    asm volatile("{\n\t.reg .pred p;\n\t"                                     \
        "mbarrier.try_wait.parity.acquire.cta.shared::cta.b64 p, [%1], %2;\n\t" \
        "selp.b32 %0, 1, 0, p;\n\t}"                                          \
        : "=r"(_d) : "r"(_m), "r"(_p) : "memory");                            \
    if (!_d) {                                                                \
        asm volatile("{\n\t.reg .pred P1;\n\t"                                \
            "W_%=:\n\t"                                                       \
            "mbarrier.try_wait.parity.acquire.cta.shared::cta.b64 P1, [%0], %1, 0x989680;\n\t" \
            "@P1 bra.uni D_%=;\n\t"                                           \
            "bra.uni W_%=;\n\t"                                               \
            "D_%=:\n\t}" :: "r"(_m), "r"(_p) : "memory");                     \
    }                                                                         \
} while (0)

__device__ __forceinline__ void bulk_g2s(uint32_t dst, const void* src,
                                         uint32_t bytes, uint32_t mbar) {
    asm volatile(
        "cp.async.bulk.shared::cta.global.mbarrier::complete_tx::bytes [%0], [%1], %2, [%3];"
        :: "r"(dst), "l"(src), "r"(bytes), "r"(mbar) : "memory");
}

#define LDSM_X4(r, addr)                                                      \
    asm volatile("ldmatrix.sync.aligned.m8n8.x4.shared.b16 {%0,%1,%2,%3}, [%4];" \
        : "=r"((r)[0]), "=r"((r)[1]), "=r"((r)[2]), "=r"((r)[3]) : "r"(addr))

#define MMA16816(d, a, b0, b1)                                                \
    asm volatile("mma.sync.aligned.m16n8k16.row.col.f32.bf16.bf16.f32 "       \
        "{%0,%1,%2,%3}, {%4,%5,%6,%7}, {%8,%9}, {%0,%1,%2,%3};"               \
        : "+f"((d)[0]), "+f"((d)[1]), "+f"((d)[2]), "+f"((d)[3])              \
        : "r"((a)[0]), "r"((a)[1]), "r"((a)[2]), "r"((a)[3]),                 \
          "r"(b0), "r"(b1))

// ---------------------------------------------------------------------------
// Kernel 1: L2-normalize + bf16 quantize, scattered into swizzled tile blocks.
// ---------------------------------------------------------------------------
__global__ void __launch_bounds__(256) norm_kernel(const float* __restrict__ feat)
{
    const int r = blockIdx.x;
    const int b = r & (NB - 1);
    const int v = r >> 11;
    const float* __restrict__ src = feat + ((size_t)b * 2 + v) * DDIM;

    const int t = threadIdx.x;
    float4 x = reinterpret_cast<const float4*>(src)[t];
    float ss = x.x * x.x + x.y * x.y + x.z * x.z + x.w * x.w;
    #pragma unroll
    for (int o = 16; o; o >>= 1) ss += __shfl_xor_sync(0xffffffffu, ss, o);
    __shared__ float ws[8];
    if ((t & 31) == 0) ws[t >> 5] = ss;
    __syncthreads();
    float tot = 0.f;
    #pragma unroll
    for (int i = 0; i < 8; ++i) tot += ws[i];
    const float inv = 1.0f / fmaxf(sqrtf(tot), 1e-12f);

    __nv_bfloat162 p01 = __floats2bfloat162_rn(x.x * inv, x.y * inv);
    __nv_bfloat162 p23 = __floats2bfloat162_rn(x.z * inv, x.w * inv);
    uint2 val;
    val.x = *reinterpret_cast<uint32_t*>(&p01);
    val.y = *reinterpret_cast<uint32_t*>(&p23);

    const int k  = t * 4;          // feature index of first element
    const int kc = k >> 6;         // which 64-col chunk
    const int rt = r >> 7;         // row tile
    const int m  = r & 127;        // row within tile
    const int c  = k & 63;         // col within chunk
    uint32_t off = (uint32_t)(m * 128 + c * 2);
    uint32_t sw  = off ^ ((off >> 3) & 0x70);   // SW128, matches ldmatrix swizzle
    *reinterpret_cast<uint2*>(g_zb + (size_t)(kc * ROW_TILES + rt) * BLK_BYTES + sw) = val;

    if (t == 0) { g_denom[r] = 0.0f; g_pos[r] = 0.0f; }
}

// ---------------------------------------------------------------------------
// Kernel 2: upper-triangular bf16 GEMM tiles + symmetric exp epilogue.
// Feed: 1-2 cp.async.bulk (16KB) per k-chunk into a 3-stage mbarrier ring.
// ---------------------------------------------------------------------------
__global__ void __launch_bounds__(256, 2) simloss_kernel()
{
    extern __shared__ __align__(1024) unsigned char dynsmem[];
    __shared__ __align__(8) unsigned long long mb_full[NSTAGE];
    const uint32_t smem_base = smem_u32(dynsmem);
    const uint32_t full0     = smem_u32(&mb_full[0]);

    // Map linear tile id -> (bi, bj) in upper triangle.
    int rem = blockIdx.x, bi = 0;
    while (rem >= 32 - bi) { rem -= 32 - bi; ++bi; }
    const int bj = bi + rem;
    const bool diag = (bi == bj);

    const int tid    = threadIdx.x;
    const int lane   = tid & 31;
    const int warp   = tid >> 5;
    const int warp_m = warp & 3;
    const int warp_n = warp >> 2;
    const int row0   = bi * BM;
    const int col0   = bj * BN;

    if (tid == 0) {
        #pragma unroll
        for (int s = 0; s < NSTAGE; ++s) MBAR_INIT(full0 + 8 * s, 1);
    }
    __syncthreads();

    auto issue_chunk = [&](int stage, int kc) {
        if (tid == 0) {
            const uint32_t bar = full0 + 8 * stage;
            const uint32_t sA  = smem_base + stage * STAGE_BYTES;
            const unsigned char* gA = g_zb + (size_t)(kc * ROW_TILES + bi) * BLK_BYTES;
            MBAR_EXPECT_TX(bar, diag ? BLK_BYTES : 2 * BLK_BYTES);
            bulk_g2s(sA, gA, BLK_BYTES, bar);
            if (!diag) {
                const unsigned char* gB = g_zb + (size_t)(kc * ROW_TILES + bj) * BLK_BYTES;
                bulk_g2s(sA + BLK_BYTES, gB, BLK_BYTES, bar);
            }
        }
    };

    float acc[2][4][2][4];
    #pragma unroll
    for (int mi = 0; mi < 2; ++mi)
        #pragma unroll
        for (int ni = 0; ni < 4; ++ni)
            #pragma unroll
            for (int h = 0; h < 2; ++h)
                #pragma unroll
                for (int e = 0; e < 4; ++e) acc[mi][ni][h][e] = 0.f;

    issue_chunk(0, 0);
    issue_chunk(1, 1);

    const uint32_t lrow = (uint32_t)(lane & 15);
    const uint32_t hi16 = (uint32_t)((lane >> 4) * 16);
    const uint32_t swz  = (lrow & 7) << 4;
    const uint32_t aRowOff = (uint32_t)((warp_m * 32 + lrow) * 128);
    const uint32_t bRowOff = (uint32_t)((diag ? 0 : BLK_BYTES) +
                                        (warp_n * 64 + lrow) * 128);

    for (int kc = 0; kc < NCHUNK; ++kc) {
        const int stage = kc % NSTAGE;
        MBAR_WAIT(full0 + 8 * stage, (kc / NSTAGE) & 1);
        __syncthreads();                 // all consumers done with stage kc-1
        if (kc + 2 < NCHUNK) issue_chunk((kc + 2) % NSTAGE, kc + 2);

        const uint32_t sBase = smem_base + stage * STAGE_BYTES;
        const uint32_t aBase = sBase + aRowOff;
        const uint32_t bBase = sBase + bRowOff;

        #pragma unroll
        for (int ks = 0; ks < 4; ++ks) {
            const uint32_t off = (uint32_t)((ks * 32 + hi16)) ^ swz;
            uint32_t a[2][4], b[4][4];
            LDSM_X4(a[0], aBase + off);
            LDSM_X4(a[1], aBase + 16 * 128 + off);
            #pragma unroll
            for (int ni = 0; ni < 4; ++ni)
                LDSM_X4(b[ni], bBase + ni * 16 * 128 + off);

            #pragma unroll
            for (int mi = 0; mi < 2; ++mi)
                #pragma unroll
                for (int ni = 0; ni < 4; ++ni) {
                    MMA16816(acc[mi][ni][0], a[mi], b[ni][0], b[ni][2]);
                    MMA16816(acc[mi][ni][1], a[mi], b[ni][1], b[ni][3]);
                }
        }
        __syncthreads();
    }

    // ---- fused symmetric epilogue ------------------------------------------
    float csum[4][2][2];
    #pragma unroll
    for (int ni = 0; ni < 4; ++ni)
        #pragma unroll
        for (int h = 0; h < 2; ++h) { csum[ni][h][0] = 0.f; csum[ni][h][1] = 0.f; }

    #pragma unroll
    for (int mi = 0; mi < 2; ++mi) {
        float rsum0 = 0.f, rsum1 = 0.f;
        const int mbase = row0 + warp_m * 32 + mi * 16 + (lane >> 2);
        #pragma unroll
        for (int ni = 0; ni < 4; ++ni)
            #pragma unroll
            for (int h = 0; h < 2; ++h) {
                const int nbase = col0 + warp_n * 64 + ni * 16 + h * 8 + (lane & 3) * 2;
                #pragma unroll
                for (int e = 0; e < 4; ++e) {
                    const int m = mbase + (e >> 1) * 8;
                    const int n = nbase + (e & 1);
                    const float v = acc[mi][ni][h][e];
                    if (!diag && n == (m ^ 2048)) { g_pos[m] = v; g_pos[n] = v; }
                    const float ev = (diag && n == m) ? 0.f : __expf(v * INV_T);
                    if (e >> 1) rsum1 += ev; else rsum0 += ev;
                    if (!diag) csum[ni][h][e & 1] += ev;
                }
            }
        rsum0 += __shfl_down_sync(0xffffffffu, rsum0, 2);
        rsum0 += __shfl_down_sync(0xffffffffu, rsum0, 1);
        rsum1 += __shfl_down_sync(0xffffffffu, rsum1, 2);
        rsum1 += __shfl_down_sync(0xffffffffu, rsum1, 1);
        if ((lane & 3) == 0) {
            atomicAdd(&g_denom[mbase], rsum0);
            atomicAdd(&g_denom[mbase + 8], rsum1);
        }
    }

    if (!diag) {
        #pragma unroll
        for (int ni = 0; ni < 4; ++ni)
            #pragma unroll
            for (int h = 0; h < 2; ++h)
                #pragma unroll
                for (int p = 0; p < 2; ++p) {
                    float c = csum[ni][h][p];
                    c += __shfl_xor_sync(0xffffffffu, c, 4);
                    c += __shfl_xor_sync(0xffffffffu, c, 8);
                    c += __shfl_xor_sync(0xffffffffu, c, 16);
                    if (lane < 4)
                        atomicAdd(&g_denom[col0 + warp_n * 64 + ni * 16 + h * 8 +
                                           lane * 2 + p], c);
                }
    }
}

// ---------------------------------------------------------------------------
// Kernel 3: finalize.
// ---------------------------------------------------------------------------
__global__ void __launch_bounds__(512) finalize_kernel(float* __restrict__ out)
{
    const int t = threadIdx.x;
    float acc = 0.f;
    for (int r = t; r < N2; r += 512)
        acc += -(g_pos[r] * INV_T - logf(g_denom[r]));
    #pragma unroll
    for (int o = 16; o; o >>= 1) acc += __shfl_xor_sync(0xffffffffu, acc, o);
    __shared__ float ws[16];
    if ((t & 31) == 0) ws[t >> 5] = acc;
    __syncthreads();
    if (t == 0) {
        float tot = 0.f;
        #pragma unroll
        for (int i = 0; i < 16; ++i) tot += ws[i];
        out[0] = tot / (float)N2;
    }
}

// ---------------------------------------------------------------------------
extern "C" void kernel_launch(void* const* d_in, const int* in_sizes, int n_in,
                              void* d_out, int out_size)
{
    const float* feat = (const float*)d_in[0];
    float* out = (float*)d_out;

    cudaFuncSetAttribute(simloss_kernel,
                         cudaFuncAttributeMaxDynamicSharedMemorySize, DYN_SMEM);

    norm_kernel<<<N2, 256>>>(feat);
    simloss_kernel<<<NTILES_UT, 256, DYN_SMEM>>>();
    finalize_kernel<<<1, 512>>>(out);
}